// round 2
// baseline (speedup 1.0000x reference)
#include <cuda_runtime.h>
#include <math.h>

#define NN 100000
#define NE 1600000
#define NT (NE + NN)
#define HID 64
#define INC 128
#define OUTC 40
#define NLAYERS 8
#define GRID_A 1024
#define BLK_A 256

// ---------------- scratch (static device globals; no cudaMalloc allowed) ----
__device__ float g_h[NN * HID];
__device__ float g_h0[NN * HID];
__device__ float g_s2[NN * HID];
__device__ int   g_degi[NN];
__device__ float g_dinv[NN];
__device__ int   g_off[NN + 1];
__device__ int   g_cursor[NN];
__device__ int2  g_edge[NT];          // {row, __float_as_int(w)} grouped by col
__device__ float g_psum[GRID_A * HID];
__device__ float g_psq[GRID_A * HID];
__device__ float g_scale[HID];
__device__ float g_shift[HID];
__device__ int   g_bsums[128];
__device__ int   g_is64;

// ---------------- edge-index dtype autodetect -------------------------------
__global__ void k_detect(const int* ei32) {
    if (threadIdx.x == 0 && blockIdx.x == 0) {
        int nz = 0;
        for (int j = 0; j < 64; j++) nz |= ei32[2 * j + 1];
        g_is64 = (nz == 0) ? 1 : 0;   // int64 values < 2^31 -> high words all 0
    }
}

__device__ __forceinline__ int load_idx(const void* ei, int which, int e) {
    if (g_is64) return (int)((const long long*)ei)[(long long)which * NE + e];
    return ((const int*)ei)[which * NE + e];
}

// ---------------- preprocessing ---------------------------------------------
__global__ void k_init() {
    int i = blockIdx.x * blockDim.x + threadIdx.x;
    if (i < NN) { g_degi[i] = 1; g_cursor[i] = 0; }  // deg starts at 1 (self loop)
}

__global__ void k_deg(const void* ei) {
    int e = blockIdx.x * blockDim.x + threadIdx.x;
    if (e < NE) {
        int c = load_idx(ei, 1, e);
        if (c >= 0 && c < NN) atomicAdd(&g_degi[c], 1);
    }
}

__global__ void k_dinv() {
    int i = blockIdx.x * blockDim.x + threadIdx.x;
    if (i < NN) g_dinv[i] = rsqrtf((float)g_degi[i]);
}

__global__ void k_scan1() {
    __shared__ int sm[1024];
    int i = blockIdx.x * 1024 + threadIdx.x;
    int v = (i < NN) ? g_degi[i] : 0;
    sm[threadIdx.x] = v;
    __syncthreads();
    for (int d = 1; d < 1024; d <<= 1) {
        int t = (threadIdx.x >= d) ? sm[threadIdx.x - d] : 0;
        __syncthreads();
        if (threadIdx.x >= d) sm[threadIdx.x] += t;
        __syncthreads();
    }
    if (i < NN) g_off[i + 1] = sm[threadIdx.x];
    if (threadIdx.x == 1023) g_bsums[blockIdx.x] = sm[1023];
}

__global__ void k_scan2(int nb) {
    if (threadIdx.x == 0 && blockIdx.x == 0) {
        int run = 0;
        for (int b = 0; b < nb; b++) { int t = g_bsums[b]; g_bsums[b] = run; run += t; }
    }
}

__global__ void k_scan3() {
    int i = blockIdx.x * blockDim.x + threadIdx.x;
    if (i < NN) g_off[i + 1] += g_bsums[i >> 10];
    if (i == 0) g_off[0] = 0;
}

__global__ void k_fill(const void* ei) {
    int i = blockIdx.x * blockDim.x + threadIdx.x;
    if (i < NE) {
        int r = load_idx(ei, 0, i);
        int c = load_idx(ei, 1, i);
        if (r < 0) r = 0; if (r >= NN) r = NN - 1;
        if (c < 0) c = 0; if (c >= NN) c = NN - 1;
        float w = g_dinv[r] * g_dinv[c];
        int p = g_off[c] + atomicAdd(&g_cursor[c], 1);
        g_edge[p] = make_int2(r, __float_as_int(w));
    } else if (i < NT) {
        int c = i - NE;
        float d = g_dinv[c];
        int p = g_off[c] + atomicAdd(&g_cursor[c], 1);
        g_edge[p] = make_int2(c, __float_as_int(d * d));
    }
}

// ---------------- input GEMM: h = h0 = relu(x @ W0 + b0) --------------------
__global__ void __launch_bounds__(256) k_in(const float* __restrict__ x,
                                            const float* __restrict__ W0,
                                            const float* __restrict__ b0) {
    __shared__ float2 Ws[INC][32];   // 32 KB
    for (int idx = threadIdx.x; idx < INC * 32; idx += blockDim.x) {
        int k = idx >> 5, j = idx & 31;
        Ws[k][j] = make_float2(W0[k * HID + 2 * j], W0[k * HID + 2 * j + 1]);
    }
    __syncthreads();
    int lane = threadIdx.x & 31;
    int gw = (blockIdx.x * blockDim.x + threadIdx.x) >> 5;
    int nw = (gridDim.x * blockDim.x) >> 5;
    float2 bv = ((const float2*)b0)[lane];
    for (int base = gw * 4; base < NN; base += nw * 4) {
        float4 xv[4];
#pragma unroll
        for (int u = 0; u < 4; u++)
            xv[u] = ((const float4*)x)[(base + u) * 32 + lane];
        float2 acc[4] = {{0, 0}, {0, 0}, {0, 0}, {0, 0}};
#pragma unroll 4
        for (int k = 0; k < INC; k++) {
            float2 wv = Ws[k][lane];
            int src = k >> 2;
#pragma unroll
            for (int u = 0; u < 4; u++) {
                float comp = ((k & 3) == 0) ? xv[u].x : ((k & 3) == 1) ? xv[u].y
                           : ((k & 3) == 2) ? xv[u].z : xv[u].w;
                float xk = __shfl_sync(0xffffffffu, comp, src);
                acc[u].x += xk * wv.x;
                acc[u].y += xk * wv.y;
            }
        }
#pragma unroll
        for (int u = 0; u < 4; u++) {
            float2 o;
            o.x = fmaxf(acc[u].x + bv.x, 0.f);
            o.y = fmaxf(acc[u].y + bv.y, 0.f);
            ((float2*)g_h)[(base + u) * 32 + lane]  = o;
            ((float2*)g_h0)[(base + u) * 32 + lane] = o;
        }
    }
}

// ---------------- per-layer: aggregate + residual + GEMM + BN partials ------
__global__ void __launch_bounds__(BLK_A) k_layer(const float* __restrict__ Wc,
                                                 float beta_l) {
    __shared__ float2 Ws[HID][32];   // 16 KB
    for (int idx = threadIdx.x; idx < HID * 32; idx += blockDim.x) {
        int k = idx >> 5, j = idx & 31;
        Ws[k][j] = make_float2(Wc[k * HID + 2 * j], Wc[k * HID + 2 * j + 1]);
    }
    __syncthreads();
    int lane = threadIdx.x & 31;
    int wid = threadIdx.x >> 5;
    int gw = (blockIdx.x * blockDim.x + threadIdx.x) >> 5;
    int nw = (gridDim.x * blockDim.x) >> 5;
    const float2* __restrict__ hp  = (const float2*)g_h;
    const float2* __restrict__ h0p = (const float2*)g_h0;
    float2* __restrict__ s2p = (float2*)g_s2;
    float2 bsum = {0, 0}, bsq = {0, 0};
    float ob = 1.0f - beta_l;

    for (int base = gw * 4; base < NN; base += nw * 4) {
        float2 s[4];
#pragma unroll
        for (int u = 0; u < 4; u++) {
            int node = base + u;
            int e0 = g_off[node], e1 = g_off[node + 1];
            float2 acc = {0.f, 0.f};
            int e = e0;
            for (; e + 4 <= e1; e += 4) {
                int2 a0 = g_edge[e], a1 = g_edge[e + 1];
                int2 a2 = g_edge[e + 2], a3 = g_edge[e + 3];
                float2 v0 = hp[a0.x * 32 + lane];
                float2 v1 = hp[a1.x * 32 + lane];
                float2 v2 = hp[a2.x * 32 + lane];
                float2 v3 = hp[a3.x * 32 + lane];
                float w0 = __int_as_float(a0.y), w1 = __int_as_float(a1.y);
                float w2 = __int_as_float(a2.y), w3 = __int_as_float(a3.y);
                acc.x = fmaf(w0, v0.x, acc.x); acc.y = fmaf(w0, v0.y, acc.y);
                acc.x = fmaf(w1, v1.x, acc.x); acc.y = fmaf(w1, v1.y, acc.y);
                acc.x = fmaf(w2, v2.x, acc.x); acc.y = fmaf(w2, v2.y, acc.y);
                acc.x = fmaf(w3, v3.x, acc.x); acc.y = fmaf(w3, v3.y, acc.y);
            }
            for (; e < e1; e++) {
                int2 a = g_edge[e];
                float2 v = hp[a.x * 32 + lane];
                float w = __int_as_float(a.y);
                acc.x = fmaf(w, v.x, acc.x);
                acc.y = fmaf(w, v.y, acc.y);
            }
            float2 h0v = h0p[node * 32 + lane];
            s[u].x = 0.9f * acc.x + 0.1f * h0v.x;
            s[u].y = 0.9f * acc.y + 0.1f * h0v.y;
        }
        float2 t[4] = {{0, 0}, {0, 0}, {0, 0}, {0, 0}};
#pragma unroll 8
        for (int k = 0; k < HID; k++) {
            float2 wv = Ws[k][lane];
            int src = k >> 1;
#pragma unroll
            for (int u = 0; u < 4; u++) {
                float sk = __shfl_sync(0xffffffffu, (k & 1) ? s[u].y : s[u].x, src);
                t[u].x = fmaf(sk, wv.x, t[u].x);
                t[u].y = fmaf(sk, wv.y, t[u].y);
            }
        }
#pragma unroll
        for (int u = 0; u < 4; u++) {
            int node = base + u;
            float2 o;
            o.x = ob * s[u].x + beta_l * t[u].x;
            o.y = ob * s[u].y + beta_l * t[u].y;
            s2p[node * 32 + lane] = o;
            bsum.x += o.x; bsum.y += o.y;
            bsq.x = fmaf(o.x, o.x, bsq.x);
            bsq.y = fmaf(o.y, o.y, bsq.y);
        }
    }

    __shared__ float2 rS[8][32], rQ[8][32];
    rS[wid][lane] = bsum; rQ[wid][lane] = bsq;
    __syncthreads();
    if (threadIdx.x < 32) {
        float2 S = rS[0][threadIdx.x], Q = rQ[0][threadIdx.x];
#pragma unroll
        for (int j = 1; j < 8; j++) {
            S.x += rS[j][threadIdx.x].x; S.y += rS[j][threadIdx.x].y;
            Q.x += rQ[j][threadIdx.x].x; Q.y += rQ[j][threadIdx.x].y;
        }
        g_psum[blockIdx.x * HID + 2 * threadIdx.x]     = S.x;
        g_psum[blockIdx.x * HID + 2 * threadIdx.x + 1] = S.y;
        g_psq[blockIdx.x * HID + 2 * threadIdx.x]      = Q.x;
        g_psq[blockIdx.x * HID + 2 * threadIdx.x + 1]  = Q.y;
    }
}

// ---------------- BN stats -> scale/shift -----------------------------------
__global__ void k_bnstat(const float* __restrict__ gamma,
                         const float* __restrict__ betab) {
    __shared__ float sS[512], sQ[512];
    int tid = threadIdx.x;
    int c = tid & 63, chunk = tid >> 6;
    float s = 0.f, q = 0.f;
    for (int b = chunk; b < GRID_A; b += 8) {
        s += g_psum[b * HID + c];
        q += g_psq[b * HID + c];
    }
    sS[tid] = s; sQ[tid] = q;
    __syncthreads();
    if (tid < 64) {
#pragma unroll
        for (int j = 1; j < 8; j++) { s += sS[tid + 64 * j]; q += sQ[tid + 64 * j]; }
        float inv = 1.0f / (float)NN;
        float mu = s * inv;
        float var = q * inv - mu * mu;
        float rs = rsqrtf(var + 1e-5f);
        float sc = rs * gamma[tid];
        g_scale[tid] = sc;
        g_shift[tid] = betab[tid] - mu * sc;
    }
}

// ---------------- BN apply + relu -> h --------------------------------------
__global__ void k_bnapply() {
    int i = blockIdx.x * blockDim.x + threadIdx.x;
    if (i < NN * 16) {
        float4 v = ((const float4*)g_s2)[i];
        int c = (i & 15) << 2;
        v.x = fmaxf(fmaf(v.x, g_scale[c],     g_shift[c]),     0.f);
        v.y = fmaxf(fmaf(v.y, g_scale[c + 1], g_shift[c + 1]), 0.f);
        v.z = fmaxf(fmaf(v.z, g_scale[c + 2], g_shift[c + 2]), 0.f);
        v.w = fmaxf(fmaf(v.w, g_scale[c + 3], g_shift[c + 3]), 0.f);
        ((float4*)g_h)[i] = v;
    }
}

// ---------------- output GEMM: out = h @ Wout + bout ------------------------
__global__ void __launch_bounds__(256) k_out(const float* __restrict__ Wout,
                                             const float* __restrict__ bout,
                                             float* __restrict__ out) {
    __shared__ float Ws[HID][OUTC];  // ~10 KB
    for (int idx = threadIdx.x; idx < HID * OUTC; idx += blockDim.x)
        Ws[idx / OUTC][idx % OUTC] = Wout[idx];
    __syncthreads();
    int lane = threadIdx.x & 31;
    int gw = (blockIdx.x * blockDim.x + threadIdx.x) >> 5;
    int nw = (gridDim.x * blockDim.x) >> 5;
    const float2* __restrict__ hp = (const float2*)g_h;
    float b0v = bout[lane];
    float b1v = (lane < 8) ? bout[32 + lane] : 0.f;
    for (int base = gw * 4; base < NN; base += nw * 4) {
        float2 hv[4];
#pragma unroll
        for (int u = 0; u < 4; u++) hv[u] = hp[(base + u) * 32 + lane];
        float a0[4] = {0, 0, 0, 0}, a1[4] = {0, 0, 0, 0};
#pragma unroll 8
        for (int k = 0; k < HID; k++) {
            float w0 = Ws[k][lane];
            float w1 = (lane < 8) ? Ws[k][32 + lane] : 0.f;
            int src = k >> 1;
#pragma unroll
            for (int u = 0; u < 4; u++) {
                float hk = __shfl_sync(0xffffffffu, (k & 1) ? hv[u].y : hv[u].x, src);
                a0[u] = fmaf(hk, w0, a0[u]);
                a1[u] = fmaf(hk, w1, a1[u]);
            }
        }
#pragma unroll
        for (int u = 0; u < 4; u++) {
            int node = base + u;
            out[node * OUTC + lane] = a0[u] + b0v;
            if (lane < 8) out[node * OUTC + 32 + lane] = a1[u] + b1v;
        }
    }
}

// ---------------- launcher --------------------------------------------------
extern "C" void kernel_launch(void* const* d_in, const int* in_sizes, int n_in,
                              void* d_out, int out_size) {
    const float* x     = (const float*)d_in[0];
    const void*  ei    = d_in[1];
    const float* W0    = (const float*)d_in[2];
    const float* b0    = (const float*)d_in[3];
    const float* convW = (const float*)d_in[4];
    const float* gam   = (const float*)d_in[5];
    const float* bet   = (const float*)d_in[6];
    const float* Wout  = (const float*)d_in[7];
    const float* bout  = (const float*)d_in[8];
    float* out = (float*)d_out;

    k_detect<<<1, 32>>>((const int*)ei);
    k_init<<<(NN + 255) / 256, 256>>>();
    k_deg<<<(NE + 255) / 256, 256>>>(ei);
    k_dinv<<<(NN + 255) / 256, 256>>>();
    int nb = (NN + 1023) / 1024;
    k_scan1<<<nb, 1024>>>();
    k_scan2<<<1, 32>>>(nb);
    k_scan3<<<(NN + 255) / 256, 256>>>();
    k_fill<<<(NT + 255) / 256, 256>>>(ei);
    k_in<<<1024, 256>>>(x, W0, b0);
    for (int l = 0; l < NLAYERS; l++) {
        float bl = logf(0.5f / (float)(l + 1) + 1.0f);
        k_layer<<<GRID_A, BLK_A>>>(convW + l * HID * HID, bl);
        k_bnstat<<<1, 512>>>(gam + l * HID, bet + l * HID);
        k_bnapply<<<(NN * 16 + 255) / 256, 256>>>();
    }
    k_out<<<1024, 256>>>(Wout, bout, out);
}

// round 3
// speedup vs baseline: 1.2834x; 1.2834x over previous
#include <cuda_runtime.h>
#include <cuda_fp16.h>
#include <math.h>

#define NN 100000
#define NE 1600000
#define NT (NE + NN)
#define HID 64
#define INC 128
#define OUTC 40
#define NLAYERS 8
#define GRID_A 592          // 148 SMs x 4 blocks -> single wave
#define BLK_A 256

// ---------------- scratch (static device globals; no cudaMalloc allowed) ----
__device__ float g_h[NN * HID];        // fp32 h (only written on last layer, for k_out)
__device__ uint2 g_hh[NN * 16];        // fp16 h: 64 halves per node (gather operand)
__device__ float g_h0[NN * HID];
__device__ float g_s2[NN * HID];
__device__ int   g_degi[NN];
__device__ int   g_off[NN + 1];
__device__ int   g_cursor[NN];
__device__ int2  g_edge[NT];           // {row, __float_as_int(w)} grouped by col
__device__ float g_psum[HID * GRID_A]; // transposed: [channel][block]
__device__ float g_psq[HID * GRID_A];
__device__ float g_scale[HID];
__device__ float g_shift[HID];
__device__ int   g_bsums[128];
__device__ int   g_is64;

// ---------------- edge-index dtype autodetect (parallel) --------------------
__global__ void k_detect(const int* ei32) {
    int lane = threadIdx.x;
    int nz = 0;
    for (int j = lane; j < 256; j += 32) nz |= ei32[2 * j + 1];
    unsigned any = __ballot_sync(0xffffffffu, nz != 0);
    if (lane == 0) g_is64 = (any == 0) ? 1 : 0;  // int64 values < 2^31 -> hi words 0
}

__device__ __forceinline__ int load_idx(const void* ei, int which, int e) {
    if (g_is64) return (int)((const long long*)ei)[(long long)which * NE + e];
    return ((const int*)ei)[which * NE + e];
}

// ---------------- preprocessing ---------------------------------------------
__global__ void k_init() {
    int i = blockIdx.x * blockDim.x + threadIdx.x;
    if (i < NN) { g_degi[i] = 1; g_cursor[i] = 0; }  // deg starts at 1 (self loop)
}

__global__ void k_deg(const void* ei) {
    int e = blockIdx.x * blockDim.x + threadIdx.x;
    if (e < NE) {
        int c = load_idx(ei, 1, e);
        if (c >= 0 && c < NN) atomicAdd(&g_degi[c], 1);
    }
}

__global__ void k_scan1() {
    __shared__ int sm[1024];
    int i = blockIdx.x * 1024 + threadIdx.x;
    int v = (i < NN) ? g_degi[i] : 0;
    sm[threadIdx.x] = v;
    __syncthreads();
    for (int d = 1; d < 1024; d <<= 1) {
        int t = (threadIdx.x >= d) ? sm[threadIdx.x - d] : 0;
        __syncthreads();
        if (threadIdx.x >= d) sm[threadIdx.x] += t;
        __syncthreads();
    }
    if (i < NN) g_off[i + 1] = sm[threadIdx.x];
    if (threadIdx.x == 1023) g_bsums[blockIdx.x] = sm[1023];
}

__global__ void k_scan2(int nb) {
    if (threadIdx.x == 0 && blockIdx.x == 0) {
        int run = 0;
        for (int b = 0; b < nb; b++) { int t = g_bsums[b]; g_bsums[b] = run; run += t; }
    }
}

__global__ void k_scan3() {
    int i = blockIdx.x * blockDim.x + threadIdx.x;
    if (i < NN) g_off[i + 1] += g_bsums[i >> 10];
    if (i == 0) g_off[0] = 0;
}

__global__ void k_fill(const void* ei) {
    int i = blockIdx.x * blockDim.x + threadIdx.x;
    if (i < NE) {
        int r = load_idx(ei, 0, i);
        int c = load_idx(ei, 1, i);
        if (r < 0) r = 0; if (r >= NN) r = NN - 1;
        if (c < 0) c = 0; if (c >= NN) c = NN - 1;
        float w = rsqrtf((float)g_degi[r]) * rsqrtf((float)g_degi[c]);
        int p = g_off[c] + atomicAdd(&g_cursor[c], 1);
        g_edge[p] = make_int2(r, __float_as_int(w));
    } else if (i < NT) {
        int c = i - NE;
        float d = rsqrtf((float)g_degi[c]);
        int p = g_off[c] + atomicAdd(&g_cursor[c], 1);
        g_edge[p] = make_int2(c, __float_as_int(d * d));
    }
}

// ---------------- input GEMM: h = h0 = relu(x @ W0 + b0) --------------------
__global__ void __launch_bounds__(256, 4) k_in(const float* __restrict__ x,
                                               const float* __restrict__ W0,
                                               const float* __restrict__ b0) {
    __shared__ float2 Ws[INC][32];   // 32 KB
    for (int idx = threadIdx.x; idx < INC * 32; idx += blockDim.x) {
        int k = idx >> 5, j = idx & 31;
        Ws[k][j] = make_float2(W0[k * HID + 2 * j], W0[k * HID + 2 * j + 1]);
    }
    __syncthreads();
    int lane = threadIdx.x & 31;
    int gw = (blockIdx.x * blockDim.x + threadIdx.x) >> 5;
    int nw = (gridDim.x * blockDim.x) >> 5;
    float2 bv = ((const float2*)b0)[lane];
    for (int base = gw * 4; base < NN; base += nw * 4) {
        float4 xv[4];
#pragma unroll
        for (int u = 0; u < 4; u++)
            xv[u] = ((const float4*)x)[(base + u) * 32 + lane];
        float2 acc[4] = {{0, 0}, {0, 0}, {0, 0}, {0, 0}};
#pragma unroll 4
        for (int k = 0; k < INC; k++) {
            float2 wv = Ws[k][lane];
            int src = k >> 2;
#pragma unroll
            for (int u = 0; u < 4; u++) {
                float comp = ((k & 3) == 0) ? xv[u].x : ((k & 3) == 1) ? xv[u].y
                           : ((k & 3) == 2) ? xv[u].z : xv[u].w;
                float xk = __shfl_sync(0xffffffffu, comp, src);
                acc[u].x += xk * wv.x;
                acc[u].y += xk * wv.y;
            }
        }
#pragma unroll
        for (int u = 0; u < 4; u++) {
            float2 o;
            o.x = fmaxf(acc[u].x + bv.x, 0.f);
            o.y = fmaxf(acc[u].y + bv.y, 0.f);
            ((__half2*)g_hh)[(base + u) * 32 + lane] = __floats2half2_rn(o.x, o.y);
            ((float2*)g_h0)[(base + u) * 32 + lane] = o;
        }
    }
}

// ---------------- per-layer: aggregate + residual + GEMM + BN partials ------
__global__ void __launch_bounds__(BLK_A, 4) k_layer(const float* __restrict__ Wc,
                                                    float beta_l) {
    __shared__ float2 Ws[HID][32];   // 16 KB
    for (int idx = threadIdx.x; idx < HID * 32; idx += blockDim.x) {
        int k = idx >> 5, j = idx & 31;
        Ws[k][j] = make_float2(Wc[k * HID + 2 * j], Wc[k * HID + 2 * j + 1]);
    }
    __syncthreads();
    int lane = threadIdx.x & 31;
    int wid = threadIdx.x >> 5;
    int gw = (blockIdx.x * blockDim.x + threadIdx.x) >> 5;
    int nw = (gridDim.x * blockDim.x) >> 5;
    const __half2* __restrict__ hh = (const __half2*)g_hh;
    const float2* __restrict__ h0p = (const float2*)g_h0;
    float2* __restrict__ s2p = (float2*)g_s2;
    float2 bsum = {0, 0}, bsq = {0, 0};
    float ob = 1.0f - beta_l;

    for (int base = gw * 4; base < NN; base += nw * 4) {
        float2 s[4];
#pragma unroll
        for (int u = 0; u < 4; u++) {
            int node = base + u;
            int e0 = g_off[node], e1 = g_off[node + 1];
            float ax = 0.f, ay = 0.f;
            for (int e = e0; e < e1; e += 8) {
                int2 a[8];
#pragma unroll
                for (int j = 0; j < 8; j++)
                    a[j] = (e + j < e1) ? g_edge[e + j] : make_int2(0, 0);
#pragma unroll
                for (int j = 0; j < 8; j++) {
                    float2 vf = __half22float2(hh[a[j].x * 32 + lane]);
                    float w = __int_as_float(a[j].y);
                    ax = fmaf(w, vf.x, ax);
                    ay = fmaf(w, vf.y, ay);
                }
            }
            float2 h0v = h0p[node * 32 + lane];
            s[u].x = 0.9f * ax + 0.1f * h0v.x;
            s[u].y = 0.9f * ay + 0.1f * h0v.y;
        }
        float2 t[4] = {{0, 0}, {0, 0}, {0, 0}, {0, 0}};
#pragma unroll 8
        for (int k = 0; k < HID; k++) {
            float2 wv = Ws[k][lane];
            int src = k >> 1;
#pragma unroll
            for (int u = 0; u < 4; u++) {
                float sk = __shfl_sync(0xffffffffu, (k & 1) ? s[u].y : s[u].x, src);
                t[u].x = fmaf(sk, wv.x, t[u].x);
                t[u].y = fmaf(sk, wv.y, t[u].y);
            }
        }
#pragma unroll
        for (int u = 0; u < 4; u++) {
            int node = base + u;
            float2 o;
            o.x = ob * s[u].x + beta_l * t[u].x;
            o.y = ob * s[u].y + beta_l * t[u].y;
            s2p[node * 32 + lane] = o;
            bsum.x += o.x; bsum.y += o.y;
            bsq.x = fmaf(o.x, o.x, bsq.x);
            bsq.y = fmaf(o.y, o.y, bsq.y);
        }
    }

    __shared__ float2 rS[8][32], rQ[8][32];
    rS[wid][lane] = bsum; rQ[wid][lane] = bsq;
    __syncthreads();
    if (threadIdx.x < 32) {
        float2 S = rS[0][threadIdx.x], Q = rQ[0][threadIdx.x];
#pragma unroll
        for (int j = 1; j < 8; j++) {
            S.x += rS[j][threadIdx.x].x; S.y += rS[j][threadIdx.x].y;
            Q.x += rQ[j][threadIdx.x].x; Q.y += rQ[j][threadIdx.x].y;
        }
        // transposed partials: [channel][block] for coalesced bnstat
        g_psum[(2 * threadIdx.x)     * GRID_A + blockIdx.x] = S.x;
        g_psum[(2 * threadIdx.x + 1) * GRID_A + blockIdx.x] = S.y;
        g_psq[(2 * threadIdx.x)      * GRID_A + blockIdx.x] = Q.x;
        g_psq[(2 * threadIdx.x + 1)  * GRID_A + blockIdx.x] = Q.y;
    }
}

// ---------------- BN stats -> scale/shift (64 blocks, one per channel) ------
__global__ void k_bnstat(const float* __restrict__ gamma,
                         const float* __restrict__ betab) {
    int c = blockIdx.x;
    int t = threadIdx.x;
    float s = 0.f, q = 0.f;
    for (int b = t; b < GRID_A; b += 256) {
        s += g_psum[c * GRID_A + b];
        q += g_psq[c * GRID_A + b];
    }
    __shared__ float sS[256], sQ[256];
    sS[t] = s; sQ[t] = q;
    __syncthreads();
    for (int d = 128; d >= 32; d >>= 1) {
        if (t < d) { sS[t] += sS[t + d]; sQ[t] += sQ[t + d]; }
        __syncthreads();
    }
    if (t < 32) {
        s = sS[t]; q = sQ[t];
#pragma unroll
        for (int o = 16; o > 0; o >>= 1) {
            s += __shfl_down_sync(0xffffffffu, s, o);
            q += __shfl_down_sync(0xffffffffu, q, o);
        }
        if (t == 0) {
            float inv = 1.0f / (float)NN;
            float mu = s * inv;
            float var = q * inv - mu * mu;
            float rs = rsqrtf(var + 1e-5f);
            float sc = rs * gamma[c];
            g_scale[c] = sc;
            g_shift[c] = betab[c] - mu * sc;
        }
    }
}

// ---------------- BN apply + relu -> h (fp16; fp32 too on last layer) -------
__global__ void k_bnapply(int writeF32) {
    int i = blockIdx.x * blockDim.x + threadIdx.x;
    if (i < NN * 16) {
        float4 v = ((const float4*)g_s2)[i];
        int c = (i & 15) << 2;
        v.x = fmaxf(fmaf(v.x, g_scale[c],     g_shift[c]),     0.f);
        v.y = fmaxf(fmaf(v.y, g_scale[c + 1], g_shift[c + 1]), 0.f);
        v.z = fmaxf(fmaf(v.z, g_scale[c + 2], g_shift[c + 2]), 0.f);
        v.w = fmaxf(fmaf(v.w, g_scale[c + 3], g_shift[c + 3]), 0.f);
        __half2 p0 = __floats2half2_rn(v.x, v.y);
        __half2 p1 = __floats2half2_rn(v.z, v.w);
        uint2 pk;
        pk.x = *reinterpret_cast<unsigned int*>(&p0);
        pk.y = *reinterpret_cast<unsigned int*>(&p1);
        g_hh[i] = pk;
        if (writeF32) ((float4*)g_h)[i] = v;
    }
}

// ---------------- output GEMM: out = h @ Wout + bout ------------------------
__global__ void __launch_bounds__(256, 4) k_out(const float* __restrict__ Wout,
                                                const float* __restrict__ bout,
                                                float* __restrict__ out) {
    __shared__ float Ws[HID][OUTC];  // ~10 KB
    for (int idx = threadIdx.x; idx < HID * OUTC; idx += blockDim.x)
        Ws[idx / OUTC][idx % OUTC] = Wout[idx];
    __syncthreads();
    int lane = threadIdx.x & 31;
    int gw = (blockIdx.x * blockDim.x + threadIdx.x) >> 5;
    int nw = (gridDim.x * blockDim.x) >> 5;
    const float2* __restrict__ hp = (const float2*)g_h;
    float b0v = bout[lane];
    float b1v = (lane < 8) ? bout[32 + lane] : 0.f;
    for (int base = gw * 4; base < NN; base += nw * 4) {
        float2 hv[4];
#pragma unroll
        for (int u = 0; u < 4; u++) hv[u] = hp[(base + u) * 32 + lane];
        float a0[4] = {0, 0, 0, 0}, a1[4] = {0, 0, 0, 0};
#pragma unroll 8
        for (int k = 0; k < HID; k++) {
            float w0 = Ws[k][lane];
            float w1 = (lane < 8) ? Ws[k][32 + lane] : 0.f;
            int src = k >> 1;
#pragma unroll
            for (int u = 0; u < 4; u++) {
                float hk = __shfl_sync(0xffffffffu, (k & 1) ? hv[u].y : hv[u].x, src);
                a0[u] = fmaf(hk, w0, a0[u]);
                a1[u] = fmaf(hk, w1, a1[u]);
            }
        }
#pragma unroll
        for (int u = 0; u < 4; u++) {
            int node = base + u;
            out[node * OUTC + lane] = a0[u] + b0v;
            if (lane < 8) out[node * OUTC + 32 + lane] = a1[u] + b1v;
        }
    }
}

// ---------------- launcher --------------------------------------------------
extern "C" void kernel_launch(void* const* d_in, const int* in_sizes, int n_in,
                              void* d_out, int out_size) {
    const float* x     = (const float*)d_in[0];
    const void*  ei    = d_in[1];
    const float* W0    = (const float*)d_in[2];
    const float* b0    = (const float*)d_in[3];
    const float* convW = (const float*)d_in[4];
    const float* gam   = (const float*)d_in[5];
    const float* bet   = (const float*)d_in[6];
    const float* Wout  = (const float*)d_in[7];
    const float* bout  = (const float*)d_in[8];
    float* out = (float*)d_out;

    k_detect<<<1, 32>>>((const int*)ei);
    k_init<<<(NN + 255) / 256, 256>>>();
    k_deg<<<(NE + 255) / 256, 256>>>(ei);
    int nb = (NN + 1023) / 1024;
    k_scan1<<<nb, 1024>>>();
    k_scan2<<<1, 32>>>(nb);
    k_scan3<<<(NN + 255) / 256, 256>>>();
    k_fill<<<(NT + 255) / 256, 256>>>(ei);
    k_in<<<GRID_A, 256>>>(x, W0, b0);
    for (int l = 0; l < NLAYERS; l++) {
        float bl = logf(0.5f / (float)(l + 1) + 1.0f);
        k_layer<<<GRID_A, BLK_A>>>(convW + l * HID * HID, bl);
        k_bnstat<<<HID, 256>>>(gam + l * HID, bet + l * HID);
        k_bnapply<<<(NN * 16 + 255) / 256, 256>>>(l == NLAYERS - 1 ? 1 : 0);
    }
    k_out<<<GRID_A, 256>>>(Wout, bout, out);
}

// round 4
// speedup vs baseline: 1.2968x; 1.0105x over previous
#include <cuda_runtime.h>
#include <cuda_fp16.h>
#include <math.h>

#define NN 100000
#define NE 1600000
#define NPAD (NE + NN + 7 * NN)   // padded edge storage
#define HID 64
#define INC 128
#define OUTC 40
#define NLAYERS 8
#define GRID_A 592          // 148 SMs x 4 blocks -> single wave
#define BLK_A 256

typedef unsigned long long u64;

__device__ __forceinline__ u64 pack2(float a, float b) {
    u64 r; asm("mov.b64 %0, {%1, %2};" : "=l"(r) : "f"(a), "f"(b)); return r;
}
__device__ __forceinline__ void unpack2(float& a, float& b, u64 v) {
    asm("mov.b64 {%0, %1}, %2;" : "=f"(a), "=f"(b) : "l"(v));
}
__device__ __forceinline__ u64 ffma2(u64 a, u64 b, u64 c) {
    u64 d; asm("fma.rn.f32x2 %0, %1, %2, %3;" : "=l"(d) : "l"(a), "l"(b), "l"(c)); return d;
}

// ---------------- scratch (static device globals; no cudaMalloc allowed) ----
__device__ float g_h[NN * HID];        // fp32 h (written on last layer, for k_out)
__device__ uint2 g_hh[NN * 16];        // fp16 h: 64 halves per node (gather operand)
__device__ float g_h0[NN * HID];
__device__ float g_s2[NN * HID];
__device__ int   g_degi[NN];
__device__ int   g_off[NN + 1];
__device__ int   g_cursor[NN];
__device__ __align__(16) int2 g_edge[NPAD];  // {row, w_bits}, grouped by col, padded %8
__device__ float g_psum[HID * GRID_A];
__device__ float g_psq[HID * GRID_A];
__device__ float g_scale[HID];
__device__ float g_shift[HID];
__device__ int   g_bsums[128];
__device__ int   g_is64;

// ---------------- edge-index dtype autodetect -------------------------------
__global__ void k_detect(const int* ei32) {
    int lane = threadIdx.x;
    int nz = 0;
    for (int j = lane; j < 256; j += 32) nz |= ei32[2 * j + 1];
    unsigned any = __ballot_sync(0xffffffffu, nz != 0);
    if (lane == 0) g_is64 = (any == 0) ? 1 : 0;
}

__device__ __forceinline__ int load_idx(const void* ei, int which, int e) {
    if (g_is64) return (int)((const long long*)ei)[(long long)which * NE + e];
    return ((const int*)ei)[which * NE + e];
}

// ---------------- preprocessing ---------------------------------------------
__global__ void k_init() {
    int i = blockIdx.x * blockDim.x + threadIdx.x;
    if (i < NN) { g_degi[i] = 1; g_cursor[i] = 0; }
}

__global__ void k_deg(const void* ei) {
    int e = blockIdx.x * blockDim.x + threadIdx.x;
    if (e < NE) {
        int c = load_idx(ei, 1, e);
        if (c >= 0 && c < NN) atomicAdd(&g_degi[c], 1);
    }
}

__global__ void k_scan1() {
    __shared__ int sm[1024];
    int i = blockIdx.x * 1024 + threadIdx.x;
    int v = (i < NN) ? ((g_degi[i] + 7) & ~7) : 0;   // pad to multiple of 8
    sm[threadIdx.x] = v;
    __syncthreads();
    for (int d = 1; d < 1024; d <<= 1) {
        int t = (threadIdx.x >= d) ? sm[threadIdx.x - d] : 0;
        __syncthreads();
        if (threadIdx.x >= d) sm[threadIdx.x] += t;
        __syncthreads();
    }
    if (i < NN) g_off[i + 1] = sm[threadIdx.x];
    if (threadIdx.x == 1023) g_bsums[blockIdx.x] = sm[1023];
}

__global__ void k_scan2(int nb) {
    if (threadIdx.x == 0 && blockIdx.x == 0) {
        int run = 0;
        for (int b = 0; b < nb; b++) { int t = g_bsums[b]; g_bsums[b] = run; run += t; }
    }
}

__global__ void k_scan3() {
    int i = blockIdx.x * blockDim.x + threadIdx.x;
    if (i < NN) g_off[i + 1] += g_bsums[i >> 10];
    if (i == 0) g_off[0] = 0;
}

__global__ void k_fill(const void* ei) {
    int i = blockIdx.x * blockDim.x + threadIdx.x;
    if (i < NE) {
        int r = load_idx(ei, 0, i);
        int c = load_idx(ei, 1, i);
        if (r < 0) r = 0; if (r >= NN) r = NN - 1;
        if (c < 0) c = 0; if (c >= NN) c = NN - 1;
        float w = rsqrtf((float)g_degi[r]) * rsqrtf((float)g_degi[c]);
        int p = g_off[c] + atomicAdd(&g_cursor[c], 1);
        g_edge[p] = make_int2(r, __float_as_int(w));
    } else if (i < NE + NN) {
        int c = i - NE;
        float d = rsqrtf((float)g_degi[c]);
        int p = g_off[c] + atomicAdd(&g_cursor[c], 1);
        g_edge[p] = make_int2(c, __float_as_int(d * d));
    }
}

__global__ void k_pad() {    // fill dummy zero-weight edges up to padded offset
    int c = blockIdx.x * blockDim.x + threadIdx.x;
    if (c < NN) {
        int s = g_off[c] + g_degi[c];
        int e = g_off[c + 1];
        for (int p = s; p < e; p++) g_edge[p] = make_int2(0, 0);
    }
}

// ---------------- input GEMM: h = h0 = relu(x @ W0 + b0) --------------------
__global__ void __launch_bounds__(256, 4) k_in(const float* __restrict__ x,
                                               const float* __restrict__ W0,
                                               const float* __restrict__ b0) {
    __shared__ float2 Ws[INC][32];   // 32 KB
    for (int idx = threadIdx.x; idx < INC * 32; idx += blockDim.x) {
        int k = idx >> 5, j = idx & 31;
        Ws[k][j] = make_float2(W0[k * HID + 2 * j], W0[k * HID + 2 * j + 1]);
    }
    __syncthreads();
    const u64* __restrict__ Wsu = reinterpret_cast<const u64*>(&Ws[0][0]);
    int lane = threadIdx.x & 31;
    int gw = (blockIdx.x * blockDim.x + threadIdx.x) >> 5;
    int nw = (gridDim.x * blockDim.x) >> 5;
    float2 bv = ((const float2*)b0)[lane];
    for (int base = gw * 4; base < NN; base += nw * 4) {
        float4 xv[4];
#pragma unroll
        for (int u = 0; u < 4; u++)
            xv[u] = ((const float4*)x)[(base + u) * 32 + lane];
        u64 acc[4] = {0, 0, 0, 0};
#pragma unroll 4
        for (int k = 0; k < INC; k++) {
            u64 wv = Wsu[k * 32 + lane];
            int src = k >> 2;
#pragma unroll
            for (int u = 0; u < 4; u++) {
                float comp = ((k & 3) == 0) ? xv[u].x : ((k & 3) == 1) ? xv[u].y
                           : ((k & 3) == 2) ? xv[u].z : xv[u].w;
                float xk = __shfl_sync(0xffffffffu, comp, src);
                acc[u] = ffma2(pack2(xk, xk), wv, acc[u]);
            }
        }
#pragma unroll
        for (int u = 0; u < 4; u++) {
            float ox, oy;
            unpack2(ox, oy, acc[u]);
            ox = fmaxf(ox + bv.x, 0.f);
            oy = fmaxf(oy + bv.y, 0.f);
            ((__half2*)g_hh)[(base + u) * 32 + lane] = __floats2half2_rn(ox, oy);
            ((float2*)g_h0)[(base + u) * 32 + lane] = make_float2(ox, oy);
        }
    }
}

// ---------------- per-layer: aggregate + residual + GEMM + BN partials ------
__global__ void __launch_bounds__(BLK_A, 4) k_layer(const float* __restrict__ Wc,
                                                    float beta_l) {
    __shared__ float2 Ws[HID][32];   // 16 KB
    for (int idx = threadIdx.x; idx < HID * 32; idx += blockDim.x) {
        int k = idx >> 5, j = idx & 31;
        Ws[k][j] = make_float2(Wc[k * HID + 2 * j], Wc[k * HID + 2 * j + 1]);
    }
    __syncthreads();
    const u64* __restrict__ Wsu = reinterpret_cast<const u64*>(&Ws[0][0]);
    int lane = threadIdx.x & 31;
    int wid = threadIdx.x >> 5;
    int hl = lane >> 4;            // half-warp id: which edge of a pair
    int cg = lane & 15;            // channel group: channels 4*cg .. 4*cg+3
    int gw = (blockIdx.x * blockDim.x + threadIdx.x) >> 5;
    int nw = (gridDim.x * blockDim.x) >> 5;
    const uint2* __restrict__ hhp = g_hh;
    const float2* __restrict__ h0p = (const float2*)g_h0;
    float2* __restrict__ s2p = (float2*)g_s2;
    float2 bsum = {0, 0}, bsq = {0, 0};
    float ob = 1.0f - beta_l;

    for (int base = gw * 4; base < NN; base += nw * 4) {
        float2 s[4];
#pragma unroll
        for (int u = 0; u < 4; u++) {
            int node = base + u;
            int e0 = g_off[node], e1 = g_off[node + 1];   // multiples of 8
            float ax = 0.f, ay = 0.f, az = 0.f, aw = 0.f;
            for (int e = e0; e < e1; e += 8) {
                const int4* qp = (const int4*)(g_edge + e);
                int4 q0 = qp[0], q1 = qp[1], q2 = qp[2], q3 = qp[3];
#define GATH(q) { \
    int r_ = hl ? q.z : q.x; \
    float w_ = __int_as_float(hl ? q.w : q.y); \
    uint2 v_ = __ldg(&hhp[r_ * 16 + cg]); \
    float2 f0_ = __half22float2(*(const __half2*)&v_.x); \
    float2 f1_ = __half22float2(*(const __half2*)&v_.y); \
    ax = fmaf(w_, f0_.x, ax); ay = fmaf(w_, f0_.y, ay); \
    az = fmaf(w_, f1_.x, az); aw = fmaf(w_, f1_.y, aw); }
                GATH(q0) GATH(q1) GATH(q2) GATH(q3)
#undef GATH
            }
            // combine the two half-warp partials (each lane ends with full sums)
            ax += __shfl_xor_sync(0xffffffffu, ax, 16);
            ay += __shfl_xor_sync(0xffffffffu, ay, 16);
            az += __shfl_xor_sync(0xffffffffu, az, 16);
            aw += __shfl_xor_sync(0xffffffffu, aw, 16);
            // reshuffle 4ch/lane(16) -> 2ch/lane(32): lane L wants ch 2L,2L+1
            int src = lane >> 1;
            float t0x = __shfl_sync(0xffffffffu, ax, src);
            float t0y = __shfl_sync(0xffffffffu, ay, src);
            float t1x = __shfl_sync(0xffffffffu, az, src);
            float t1y = __shfl_sync(0xffffffffu, aw, src);
            float gx = (lane & 1) ? t1x : t0x;
            float gy = (lane & 1) ? t1y : t0y;
            float2 h0v = h0p[node * 32 + lane];
            s[u].x = 0.9f * gx + 0.1f * h0v.x;
            s[u].y = 0.9f * gy + 0.1f * h0v.y;
        }
        u64 t[4] = {0, 0, 0, 0};
#pragma unroll 8
        for (int k = 0; k < HID; k++) {
            u64 wv = Wsu[k * 32 + lane];
            int src = k >> 1;
#pragma unroll
            for (int u = 0; u < 4; u++) {
                float sk = __shfl_sync(0xffffffffu, (k & 1) ? s[u].y : s[u].x, src);
                t[u] = ffma2(pack2(sk, sk), wv, t[u]);
            }
        }
#pragma unroll
        for (int u = 0; u < 4; u++) {
            int node = base + u;
            float tx, ty;
            unpack2(tx, ty, t[u]);
            float2 o;
            o.x = ob * s[u].x + beta_l * tx;
            o.y = ob * s[u].y + beta_l * ty;
            s2p[node * 32 + lane] = o;
            bsum.x += o.x; bsum.y += o.y;
            bsq.x = fmaf(o.x, o.x, bsq.x);
            bsq.y = fmaf(o.y, o.y, bsq.y);
        }
    }

    __shared__ float2 rS[8][32], rQ[8][32];
    rS[wid][lane] = bsum; rQ[wid][lane] = bsq;
    __syncthreads();
    if (threadIdx.x < 32) {
        float2 S = rS[0][threadIdx.x], Q = rQ[0][threadIdx.x];
#pragma unroll
        for (int j = 1; j < 8; j++) {
            S.x += rS[j][threadIdx.x].x; S.y += rS[j][threadIdx.x].y;
            Q.x += rQ[j][threadIdx.x].x; Q.y += rQ[j][threadIdx.x].y;
        }
        g_psum[(2 * threadIdx.x)     * GRID_A + blockIdx.x] = S.x;
        g_psum[(2 * threadIdx.x + 1) * GRID_A + blockIdx.x] = S.y;
        g_psq[(2 * threadIdx.x)      * GRID_A + blockIdx.x] = Q.x;
        g_psq[(2 * threadIdx.x + 1)  * GRID_A + blockIdx.x] = Q.y;
    }
}

// ---------------- BN stats -> scale/shift (64 blocks, one per channel) ------
__global__ void k_bnstat(const float* __restrict__ gamma,
                         const float* __restrict__ betab) {
    int c = blockIdx.x;
    int t = threadIdx.x;
    float s = 0.f, q = 0.f;
    for (int b = t; b < GRID_A; b += 256) {
        s += g_psum[c * GRID_A + b];
        q += g_psq[c * GRID_A + b];
    }
    __shared__ float sS[256], sQ[256];
    sS[t] = s; sQ[t] = q;
    __syncthreads();
    for (int d = 128; d >= 32; d >>= 1) {
        if (t < d) { sS[t] += sS[t + d]; sQ[t] += sQ[t + d]; }
        __syncthreads();
    }
    if (t < 32) {
        s = sS[t]; q = sQ[t];
#pragma unroll
        for (int o = 16; o > 0; o >>= 1) {
            s += __shfl_down_sync(0xffffffffu, s, o);
            q += __shfl_down_sync(0xffffffffu, q, o);
        }
        if (t == 0) {
            float inv = 1.0f / (float)NN;
            float mu = s * inv;
            float var = q * inv - mu * mu;
            float rs = rsqrtf(var + 1e-5f);
            float sc = rs * gamma[c];
            g_scale[c] = sc;
            g_shift[c] = betab[c] - mu * sc;
        }
    }
}

// ---------------- BN apply + relu -> hh (fp16; fp32 too on last layer) ------
__global__ void k_bnapply(int writeF32) {
    int i = blockIdx.x * blockDim.x + threadIdx.x;
    if (i < NN * 16) {
        float4 v = ((const float4*)g_s2)[i];
        int c = (i & 15) << 2;
        v.x = fmaxf(fmaf(v.x, g_scale[c],     g_shift[c]),     0.f);
        v.y = fmaxf(fmaf(v.y, g_scale[c + 1], g_shift[c + 1]), 0.f);
        v.z = fmaxf(fmaf(v.z, g_scale[c + 2], g_shift[c + 2]), 0.f);
        v.w = fmaxf(fmaf(v.w, g_scale[c + 3], g_shift[c + 3]), 0.f);
        __half2 p0 = __floats2half2_rn(v.x, v.y);
        __half2 p1 = __floats2half2_rn(v.z, v.w);
        uint2 pk;
        pk.x = *reinterpret_cast<unsigned int*>(&p0);
        pk.y = *reinterpret_cast<unsigned int*>(&p1);
        g_hh[i] = pk;
        if (writeF32) ((float4*)g_h)[i] = v;
    }
}

// ---------------- output GEMM: out = h @ Wout + bout ------------------------
__global__ void __launch_bounds__(256, 4) k_out(const float* __restrict__ Wout,
                                                const float* __restrict__ bout,
                                                float* __restrict__ out) {
    __shared__ float2 Wo[HID][32];   // packed {W[k][lane], W[k][32+lane] or 0}
    for (int idx = threadIdx.x; idx < HID * 32; idx += blockDim.x) {
        int k = idx >> 5, j = idx & 31;
        float w0 = Wout[k * OUTC + j];
        float w1 = (j < 8) ? Wout[k * OUTC + 32 + j] : 0.f;
        Wo[k][j] = make_float2(w0, w1);
    }
    __syncthreads();
    const u64* __restrict__ Wou = reinterpret_cast<const u64*>(&Wo[0][0]);
    int lane = threadIdx.x & 31;
    int gw = (blockIdx.x * blockDim.x + threadIdx.x) >> 5;
    int nw = (gridDim.x * blockDim.x) >> 5;
    const float2* __restrict__ hp = (const float2*)g_h;
    float b0v = bout[lane];
    float b1v = (lane < 8) ? bout[32 + lane] : 0.f;
    for (int base = gw * 4; base < NN; base += nw * 4) {
        float2 hv[4];
#pragma unroll
        for (int u = 0; u < 4; u++) hv[u] = hp[(base + u) * 32 + lane];
        u64 acc[4] = {0, 0, 0, 0};
#pragma unroll 8
        for (int k = 0; k < HID; k++) {
            u64 wv = Wou[k * 32 + lane];
            int src = k >> 1;
#pragma unroll
            for (int u = 0; u < 4; u++) {
                float hk = __shfl_sync(0xffffffffu, (k & 1) ? hv[u].y : hv[u].x, src);
                acc[u] = ffma2(pack2(hk, hk), wv, acc[u]);
            }
        }
#pragma unroll
        for (int u = 0; u < 4; u++) {
            int node = base + u;
            float a0, a1;
            unpack2(a0, a1, acc[u]);
            out[node * OUTC + lane] = a0 + b0v;
            if (lane < 8) out[node * OUTC + 32 + lane] = a1 + b1v;
        }
    }
}

// ---------------- launcher --------------------------------------------------
extern "C" void kernel_launch(void* const* d_in, const int* in_sizes, int n_in,
                              void* d_out, int out_size) {
    const float* x     = (const float*)d_in[0];
    const void*  ei    = d_in[1];
    const float* W0    = (const float*)d_in[2];
    const float* b0    = (const float*)d_in[3];
    const float* convW = (const float*)d_in[4];
    const float* gam   = (const float*)d_in[5];
    const float* bet   = (const float*)d_in[6];
    const float* Wout  = (const float*)d_in[7];
    const float* bout  = (const float*)d_in[8];
    float* out = (float*)d_out;

    k_detect<<<1, 32>>>((const int*)ei);
    k_init<<<(NN + 255) / 256, 256>>>();
    k_deg<<<(NE + 255) / 256, 256>>>(ei);
    int nb = (NN + 1023) / 1024;
    k_scan1<<<nb, 1024>>>();
    k_scan2<<<1, 32>>>(nb);
    k_scan3<<<(NN + 255) / 256, 256>>>();
    k_fill<<<(NE + NN + 255) / 256, 256>>>(ei);
    k_pad<<<(NN + 255) / 256, 256>>>();
    k_in<<<GRID_A, 256>>>(x, W0, b0);
    for (int l = 0; l < NLAYERS; l++) {
        float bl = logf(0.5f / (float)(l + 1) + 1.0f);
        k_layer<<<GRID_A, BLK_A>>>(convW + l * HID * HID, bl);
        k_bnstat<<<HID, 256>>>(gam + l * HID, bet + l * HID);
        k_bnapply<<<(NN * 16 + 255) / 256, 256>>>(l == NLAYERS - 1 ? 1 : 0);
    }
    k_out<<<GRID_A, 256>>>(Wout, bout, out);
}

// round 6
// speedup vs baseline: 1.3244x; 1.0213x over previous
#include <cuda_runtime.h>
#include <cuda_fp16.h>
#include <math.h>

#define NN 100000
#define NE 1600000
#define NPAD (NE + 8 * NN)     // edges padded to multiple of 8 per node
#define HID 64
#define INC 128
#define OUTC 40
#define NLAYERS 8
#define GRID_L 444             // 148 SMs x 3 blocks (k_layer occupancy) -> 1 wave
#define GRID_E 592             // 148 x 4 for lighter kernels
#define BLK 256

typedef unsigned long long u64;

__device__ __forceinline__ u64 pack2(float a, float b) {
    u64 r; asm("mov.b64 %0, {%1, %2};" : "=l"(r) : "f"(a), "f"(b)); return r;
}
__device__ __forceinline__ void unpack2(float& a, float& b, u64 v) {
    asm("mov.b64 {%0, %1}, %2;" : "=f"(a), "=f"(b) : "l"(v));
}
__device__ __forceinline__ u64 ffma2(u64 a, u64 b, u64 c) {
    u64 d; asm("fma.rn.f32x2 %0, %1, %2, %3;" : "=l"(d) : "l"(a), "l"(b), "l"(c)); return d;
}

// ---------------- scratch ----------------------------------------------------
__device__ float g_h[NN * HID];
__device__ uint2 g_hh[NN * 16];
__device__ float g_h0[NN * HID];
__device__ float g_s2[NN * HID];
__device__ int   g_degi[NN];
__device__ __align__(16) int g_off[NN + 4];
__device__ int   g_cursor[NN];
__device__ __align__(16) int2 g_edge[NPAD];
__device__ float g_bnS[2][HID];
__device__ float g_bnQ[2][HID];
__device__ u64   g_tdesc[128];     // decoupled-lookback: {flag<<32 | value}
__device__ int   g_tctr;
__device__ int   g_is64;

__device__ __forceinline__ int load_idx(const void* ei, int which, int e) {
    if (g_is64) return (int)((const long long*)ei)[(long long)which * NE + e];
    return ((const int*)ei)[which * NE + e];
}

// ---- launch 0: init + dtype detect + scan/bn resets -------------------------
__global__ void k_init(const int* ei32) {
    int i = blockIdx.x * blockDim.x + threadIdx.x;
    if (i < NN) { g_degi[i] = 1; g_cursor[i] = 0; }
    if (blockIdx.x == 0) {
        int t = threadIdx.x;
        if (t < 32) {
            int nz = 0;
            for (int j = t; j < 256; j += 32) nz |= ei32[2 * j + 1];
            unsigned any = __ballot_sync(0xffffffffu, nz != 0);
            if (t == 0) g_is64 = (any == 0) ? 1 : 0;
        }
        if (t >= 32 && t < 160) g_tdesc[t - 32] = 0ULL;
        if (t == 160) g_tctr = 0;
        if (t >= 192 && t < 256) { g_bnS[0][t - 192] = 0.f; g_bnQ[0][t - 192] = 0.f; }
    }
}

// ---- launch 1: degree histogram + pre-zero padded edge array ----------------
__global__ void k_degzero(const void* ei) {
    int i = blockIdx.x * blockDim.x + threadIdx.x;
    if (i < NPAD / 2) ((int4*)g_edge)[i] = make_int4(0, 0, 0, 0);
    if (i < NE) {
        int c = load_idx(ei, 1, i);
        if (c >= 0 && c < NN) atomicAdd(&g_degi[c], 1);
    }
}

// ---- launch 2: single-kernel decoupled-lookback scan ------------------------
__global__ void k_scan() {
    __shared__ int sm[1024];
    __shared__ int s_tile, s_prefix;
    if (threadIdx.x == 0) s_tile = atomicAdd(&g_tctr, 1);
    __syncthreads();
    int tile = s_tile;
    int i = tile * 1024 + threadIdx.x;
    int v = (i < NN) ? ((g_degi[i] + 7) & ~7) : 0;    // pad to multiple of 8
    sm[threadIdx.x] = v;
    __syncthreads();
    for (int d = 1; d < 1024; d <<= 1) {
        int t = (threadIdx.x >= d) ? sm[threadIdx.x - d] : 0;
        __syncthreads();
        if (threadIdx.x >= d) sm[threadIdx.x] += t;
        __syncthreads();
    }
    if (threadIdx.x == 0) {
        int total = sm[1023];
        if (tile == 0) {
            atomicExch(&g_tdesc[0], (2ULL << 32) | (unsigned)total);
            s_prefix = 0;
        } else {
            atomicExch(&g_tdesc[tile], (1ULL << 32) | (unsigned)total);
            int pfx = 0;
            for (int t = tile - 1; t >= 0; t--) {
                u64 d;
                do { d = atomicAdd(&g_tdesc[t], 0ULL); } while ((d >> 32) == 0);
                pfx += (int)(d & 0xffffffffULL);
                if ((d >> 32) == 2) break;
            }
            atomicExch(&g_tdesc[tile], (2ULL << 32) | (unsigned)(pfx + total));
            s_prefix = pfx;
        }
    }
    __syncthreads();
    int pfx = s_prefix;
    if (i < NN) g_off[i + 1] = pfx + sm[threadIdx.x];
    if (tile == 0 && threadIdx.x == 0) g_off[0] = 0;
}

// ---- launch 3: fill CSC edge list (self loops appended) ---------------------
__global__ void k_fill(const void* ei) {
    int i = blockIdx.x * blockDim.x + threadIdx.x;
    if (i < NE) {
        int r = load_idx(ei, 0, i);
        int c = load_idx(ei, 1, i);
        if (r < 0) r = 0; if (r >= NN) r = NN - 1;
        if (c < 0) c = 0; if (c >= NN) c = NN - 1;
        float w = rsqrtf((float)g_degi[r]) * rsqrtf((float)g_degi[c]);
        int p = g_off[c] + atomicAdd(&g_cursor[c], 1);
        g_edge[p] = make_int2(r, __float_as_int(w));
    } else if (i < NE + NN) {
        int c = i - NE;
        float d = rsqrtf((float)g_degi[c]);
        int p = g_off[c] + atomicAdd(&g_cursor[c], 1);
        g_edge[p] = make_int2(c, __float_as_int(d * d));
    }
}

// ---- launch 4: input GEMM h = h0 = relu(x @ W0 + b0) ------------------------
__global__ void __launch_bounds__(256, 4) k_in(const float* __restrict__ x,
                                               const float* __restrict__ W0,
                                               const float* __restrict__ b0) {
    __shared__ float2 Ws[INC][32];
    for (int idx = threadIdx.x; idx < INC * 32; idx += blockDim.x) {
        int k = idx >> 5, j = idx & 31;
        Ws[k][j] = make_float2(W0[k * HID + 2 * j], W0[k * HID + 2 * j + 1]);
    }
    __syncthreads();
    const u64* __restrict__ Wsu = reinterpret_cast<const u64*>(&Ws[0][0]);
    int lane = threadIdx.x & 31;
    int gw = (blockIdx.x * blockDim.x + threadIdx.x) >> 5;
    int nw = (gridDim.x * blockDim.x) >> 5;
    float2 bv = ((const float2*)b0)[lane];
    for (int base = gw * 4; base < NN; base += nw * 4) {
        float4 xv[4];
#pragma unroll
        for (int u = 0; u < 4; u++)
            xv[u] = ((const float4*)x)[(base + u) * 32 + lane];
        u64 acc[4] = {0, 0, 0, 0};
#pragma unroll 4
        for (int k = 0; k < INC; k++) {
            u64 wv = Wsu[k * 32 + lane];
            int src = k >> 2;
#pragma unroll
            for (int u = 0; u < 4; u++) {
                float comp = ((k & 3) == 0) ? xv[u].x : ((k & 3) == 1) ? xv[u].y
                           : ((k & 3) == 2) ? xv[u].z : xv[u].w;
                float xk = __shfl_sync(0xffffffffu, comp, src);
                acc[u] = ffma2(pack2(xk, xk), wv, acc[u]);
            }
        }
#pragma unroll
        for (int u = 0; u < 4; u++) {
            float ox, oy;
            unpack2(ox, oy, acc[u]);
            ox = fmaxf(ox + bv.x, 0.f);
            oy = fmaxf(oy + bv.y, 0.f);
            ((__half2*)g_hh)[(base + u) * 32 + lane] = __floats2half2_rn(ox, oy);
            ((float2*)g_h0)[(base + u) * 32 + lane] = make_float2(ox, oy);
        }
    }
}

// ---- launch 5 (+2/layer): aggregate + residual + GEMM + BN atomics ----------
__global__ void __launch_bounds__(BLK, 3) k_layer(const float* __restrict__ Wc,
                                                  float beta_l, int par) {
    __shared__ float2 Ws[HID][32];
    for (int idx = threadIdx.x; idx < HID * 32; idx += blockDim.x) {
        int k = idx >> 5, j = idx & 31;
        Ws[k][j] = make_float2(Wc[k * HID + 2 * j], Wc[k * HID + 2 * j + 1]);
    }
    __syncthreads();
    const u64* __restrict__ Wsu = reinterpret_cast<const u64*>(&Ws[0][0]);
    int lane = threadIdx.x & 31;
    int wid = threadIdx.x >> 5;
    int hl = lane >> 4;
    int cg = lane & 15;
    int gw = (blockIdx.x * blockDim.x + threadIdx.x) >> 5;
    int nw = (gridDim.x * blockDim.x) >> 5;
    const uint2* __restrict__ hhp = g_hh;
    const float2* __restrict__ h0p = (const float2*)g_h0;
    float2* __restrict__ s2p = (float2*)g_s2;
    float2 bsum = {0, 0}, bsq = {0, 0};
    float ob = 1.0f - beta_l;

    for (int base = gw * 4; base < NN; base += nw * 4) {
        int4 o4 = *(const int4*)&g_off[base];
        int o5 = g_off[base + 4];
        int offv[5] = {o4.x, o4.y, o4.z, o4.w, o5};
        float2 s[4];
#pragma unroll
        for (int u = 0; u < 4; u++) {
            int node = base + u;
            int e0 = offv[u], e1 = offv[u + 1];
            float ax = 0.f, ay = 0.f, az = 0.f, aw = 0.f;
#define GATH(q) { \
    int r_ = hl ? q.z : q.x; \
    float w_ = __int_as_float(hl ? q.w : q.y); \
    uint2 v_ = __ldg(&hhp[r_ * 16 + cg]); \
    float2 f0_ = __half22float2(*(const __half2*)&v_.x); \
    float2 f1_ = __half22float2(*(const __half2*)&v_.y); \
    ax = fmaf(w_, f0_.x, ax); ay = fmaf(w_, f0_.y, ay); \
    az = fmaf(w_, f1_.x, az); aw = fmaf(w_, f1_.y, aw); }
            int e = e0;
            for (; e + 16 <= e1; e += 16) {
                const int4* qp = (const int4*)(g_edge + e);
                int4 q0 = qp[0], q1 = qp[1], q2 = qp[2], q3 = qp[3];
                int4 q4 = qp[4], q5 = qp[5], q6 = qp[6], q7 = qp[7];
                GATH(q0) GATH(q1) GATH(q2) GATH(q3)
                GATH(q4) GATH(q5) GATH(q6) GATH(q7)
            }
            if (e < e1) {     // exactly 8 remaining (lists padded to %8)
                const int4* qp = (const int4*)(g_edge + e);
                int4 q0 = qp[0], q1 = qp[1], q2 = qp[2], q3 = qp[3];
                GATH(q0) GATH(q1) GATH(q2) GATH(q3)
            }
#undef GATH
            ax += __shfl_xor_sync(0xffffffffu, ax, 16);
            ay += __shfl_xor_sync(0xffffffffu, ay, 16);
            az += __shfl_xor_sync(0xffffffffu, az, 16);
            aw += __shfl_xor_sync(0xffffffffu, aw, 16);
            int src = lane >> 1;
            float t0x = __shfl_sync(0xffffffffu, ax, src);
            float t0y = __shfl_sync(0xffffffffu, ay, src);
            float t1x = __shfl_sync(0xffffffffu, az, src);
            float t1y = __shfl_sync(0xffffffffu, aw, src);
            float gx = (lane & 1) ? t1x : t0x;
            float gy = (lane & 1) ? t1y : t0y;
            float2 h0v = h0p[node * 32 + lane];
            s[u].x = 0.9f * gx + 0.1f * h0v.x;
            s[u].y = 0.9f * gy + 0.1f * h0v.y;
        }
        u64 t[4] = {0, 0, 0, 0};
#pragma unroll 8
        for (int k = 0; k < HID; k++) {
            u64 wv = Wsu[k * 32 + lane];
            int src = k >> 1;
#pragma unroll
            for (int u = 0; u < 4; u++) {
                float sk = __shfl_sync(0xffffffffu, (k & 1) ? s[u].y : s[u].x, src);
                t[u] = ffma2(pack2(sk, sk), wv, t[u]);
            }
        }
#pragma unroll
        for (int u = 0; u < 4; u++) {
            int node = base + u;
            float tx, ty;
            unpack2(tx, ty, t[u]);
            float2 o;
            o.x = ob * s[u].x + beta_l * tx;
            o.y = ob * s[u].y + beta_l * ty;
            s2p[node * 32 + lane] = o;
            bsum.x += o.x; bsum.y += o.y;
            bsq.x = fmaf(o.x, o.x, bsq.x);
            bsq.y = fmaf(o.y, o.y, bsq.y);
        }
    }

    __shared__ float2 rS[8][32], rQ[8][32];
    rS[wid][lane] = bsum; rQ[wid][lane] = bsq;
    __syncthreads();
    if (threadIdx.x < 32) {
        float2 S = rS[0][threadIdx.x], Q = rQ[0][threadIdx.x];
#pragma unroll
        for (int j = 1; j < 8; j++) {
            S.x += rS[j][threadIdx.x].x; S.y += rS[j][threadIdx.x].y;
            Q.x += rQ[j][threadIdx.x].x; Q.y += rQ[j][threadIdx.x].y;
        }
        atomicAdd(&g_bnS[par][2 * threadIdx.x],     S.x);
        atomicAdd(&g_bnS[par][2 * threadIdx.x + 1], S.y);
        atomicAdd(&g_bnQ[par][2 * threadIdx.x],     Q.x);
        atomicAdd(&g_bnQ[par][2 * threadIdx.x + 1], Q.y);
    }
}

// ---- BN scale/shift + apply + relu; zeroes next layer's accumulators --------
__global__ void __launch_bounds__(256, 4) k_bnapply(const float* __restrict__ gamma,
                                                    const float* __restrict__ betab,
                                                    int par, int writeF32) {
    __shared__ float s_scale[HID], s_shift[HID];
    int t = threadIdx.x;
    if (t < HID) {
        float inv = 1.0f / (float)NN;
        float mu = g_bnS[par][t] * inv;
        float var = g_bnQ[par][t] * inv - mu * mu;
        float rs = rsqrtf(var + 1e-5f);
        float sc = rs * gamma[t];
        s_scale[t] = sc;
        s_shift[t] = betab[t] - mu * sc;
    } else if (t < 2 * HID) {
        g_bnS[par ^ 1][t - HID] = 0.f;   // all blocks write 0: benign
        g_bnQ[par ^ 1][t - HID] = 0.f;
    }
    __syncthreads();
    for (int i = blockIdx.x * blockDim.x + threadIdx.x; i < NN * 16;
         i += gridDim.x * blockDim.x) {
        float4 v = ((const float4*)g_s2)[i];
        int c = (i & 15) << 2;
        v.x = fmaxf(fmaf(v.x, s_scale[c],     s_shift[c]),     0.f);
        v.y = fmaxf(fmaf(v.y, s_scale[c + 1], s_shift[c + 1]), 0.f);
        v.z = fmaxf(fmaf(v.z, s_scale[c + 2], s_shift[c + 2]), 0.f);
        v.w = fmaxf(fmaf(v.w, s_scale[c + 3], s_shift[c + 3]), 0.f);
        __half2 p0 = __floats2half2_rn(v.x, v.y);
        __half2 p1 = __floats2half2_rn(v.z, v.w);
        uint2 pk;
        pk.x = *reinterpret_cast<unsigned int*>(&p0);
        pk.y = *reinterpret_cast<unsigned int*>(&p1);
        g_hh[i] = pk;
        if (writeF32) ((float4*)g_h)[i] = v;
    }
}

// ---- output GEMM: out = h @ Wout + bout -------------------------------------
__global__ void __launch_bounds__(256, 4) k_out(const float* __restrict__ Wout,
                                                const float* __restrict__ bout,
                                                float* __restrict__ out) {
    __shared__ float2 Wo[HID][32];
    for (int idx = threadIdx.x; idx < HID * 32; idx += blockDim.x) {
        int k = idx >> 5, j = idx & 31;
        float w0 = Wout[k * OUTC + j];
        float w1 = (j < 8) ? Wout[k * OUTC + 32 + j] : 0.f;
        Wo[k][j] = make_float2(w0, w1);
    }
    __syncthreads();
    const u64* __restrict__ Wou = reinterpret_cast<const u64*>(&Wo[0][0]);
    int lane = threadIdx.x & 31;
    int gw = (blockIdx.x * blockDim.x + threadIdx.x) >> 5;
    int nw = (gridDim.x * blockDim.x) >> 5;
    const float2* __restrict__ hp = (const float2*)g_h;
    float b0v = bout[lane];
    float b1v = (lane < 8) ? bout[32 + lane] : 0.f;
    for (int base = gw * 4; base < NN; base += nw * 4) {
        float2 hv[4];
#pragma unroll
        for (int u = 0; u < 4; u++) hv[u] = hp[(base + u) * 32 + lane];
        u64 acc[4] = {0, 0, 0, 0};
#pragma unroll 8
        for (int k = 0; k < HID; k++) {
            u64 wv = Wou[k * 32 + lane];
            int src = k >> 1;
#pragma unroll
            for (int u = 0; u < 4; u++) {
                float hk = __shfl_sync(0xffffffffu, (k & 1) ? hv[u].y : hv[u].x, src);
                acc[u] = ffma2(pack2(hk, hk), wv, acc[u]);
            }
        }
#pragma unroll
        for (int u = 0; u < 4; u++) {
            int node = base + u;
            float a0, a1;
            unpack2(a0, a1, acc[u]);
            out[node * OUTC + lane] = a0 + b0v;
            if (lane < 8) out[node * OUTC + 32 + lane] = a1 + b1v;
        }
    }
}

// ---- launcher ---------------------------------------------------------------
extern "C" void kernel_launch(void* const* d_in, const int* in_sizes, int n_in,
                              void* d_out, int out_size) {
    const float* x     = (const float*)d_in[0];
    const void*  ei    = d_in[1];
    const float* W0    = (const float*)d_in[2];
    const float* b0    = (const float*)d_in[3];
    const float* convW = (const float*)d_in[4];
    const float* gam   = (const float*)d_in[5];
    const float* bet   = (const float*)d_in[6];
    const float* Wout  = (const float*)d_in[7];
    const float* bout  = (const float*)d_in[8];
    float* out = (float*)d_out;

    k_init<<<(NN + 255) / 256, 256>>>((const int*)ei);                 // 0
    k_degzero<<<(NE + 255) / 256, 256>>>(ei);                          // 1
    k_scan<<<(NN + 1023) / 1024, 1024>>>();                            // 2
    k_fill<<<(NE + NN + 255) / 256, 256>>>(ei);                        // 3
    k_in<<<GRID_E, 256>>>(x, W0, b0);                                  // 4
    for (int l = 0; l < NLAYERS; l++) {
        float bl = logf(0.5f / (float)(l + 1) + 1.0f);
        k_layer<<<GRID_L, BLK>>>(convW + l * HID * HID, bl, l & 1);    // 5 = k_layer(0)
        k_bnapply<<<GRID_E, 256>>>(gam + l * HID, bet + l * HID, l & 1,
                                   l == NLAYERS - 1 ? 1 : 0);
    }
    k_out<<<GRID_E, 256>>>(Wout, bout, out);
}